// round 2
// baseline (speedup 1.0000x reference)
#include <cuda_runtime.h>
#include <cuda_bf16.h>
#include <stdint.h>

#define B_ROWS   4096
#define D_MODEL  768
#define DICT     24576
#define K_TOP    64
#define CAND_CAP 512
#define MARGIN   4e-3f

// ---------------- scratch (device globals: allocation-free rule) ----------------
__device__ float g_pre[(size_t)B_ROWS * DICT];     // 402 MB pre-activations
__device__ float g_wdt[(size_t)DICT * D_MODEL];    // 75 MB  W_dec transposed [f][d]
__device__ int   g_idx[(size_t)B_ROWS * K_TOP];
__device__ float g_val[(size_t)B_ROWS * K_TOP];

// ---------------- K0: transpose W_dec [D][F] -> g_wdt [F][D] ----------------
__global__ void transpose_wdec_kernel(const float* __restrict__ wdec) {
    __shared__ float s[32][33];
    int f0 = blockIdx.x * 32;
    int d0 = blockIdx.y * 32;
    int tx = threadIdx.x, ty = threadIdx.y;
#pragma unroll
    for (int i = 0; i < 4; i++) {
        int d = d0 + ty + i * 8;
        s[ty + i * 8][tx] = wdec[(size_t)d * DICT + f0 + tx];
    }
    __syncthreads();
#pragma unroll
    for (int i = 0; i < 4; i++) {
        int f = f0 + ty + i * 8;
        g_wdt[(size_t)f * D_MODEL + d0 + tx] = s[tx][ty + i * 8];
    }
}

// ---------------- K1: SGEMM  pre = x @ W_enc^T + b_enc ----------------
__global__ __launch_bounds__(256, 2)
void sgemm_enc_kernel(const float* __restrict__ x,
                      const float* __restrict__ wenc,
                      const float* __restrict__ benc) {
    __shared__ float As[16][132];
    __shared__ float Bs[16][132];

    const int tid = threadIdx.x;
    const int tx = tid & 15;
    const int ty = tid >> 4;

    const float* Ap = x    + (size_t)(blockIdx.y * 128) * D_MODEL;
    const float* Bp = wenc + (size_t)(blockIdx.x * 128) * D_MODEL;

    float acc[8][8];
#pragma unroll
    for (int i = 0; i < 8; i++)
#pragma unroll
        for (int j = 0; j < 8; j++) acc[i][j] = 0.f;

    for (int k0 = 0; k0 < D_MODEL; k0 += 16) {
#pragma unroll
        for (int i = 0; i < 2; i++) {
            int li = tid + (i << 8);
            int r  = li >> 2;
            int c4 = li & 3;
            float4 av = *(const float4*)(Ap + (size_t)r * D_MODEL + k0 + (c4 << 2));
            As[(c4 << 2) + 0][r] = av.x;
            As[(c4 << 2) + 1][r] = av.y;
            As[(c4 << 2) + 2][r] = av.z;
            As[(c4 << 2) + 3][r] = av.w;
            float4 bv = *(const float4*)(Bp + (size_t)r * D_MODEL + k0 + (c4 << 2));
            Bs[(c4 << 2) + 0][r] = bv.x;
            Bs[(c4 << 2) + 1][r] = bv.y;
            Bs[(c4 << 2) + 2][r] = bv.z;
            Bs[(c4 << 2) + 3][r] = bv.w;
        }
        __syncthreads();

#pragma unroll
        for (int kk = 0; kk < 16; kk++) {
            float a[8], b[8];
            float4 a0 = *(const float4*)&As[kk][ty * 8];
            float4 a1 = *(const float4*)&As[kk][ty * 8 + 4];
            float4 b0 = *(const float4*)&Bs[kk][tx * 8];
            float4 b1 = *(const float4*)&Bs[kk][tx * 8 + 4];
            a[0]=a0.x;a[1]=a0.y;a[2]=a0.z;a[3]=a0.w;a[4]=a1.x;a[5]=a1.y;a[6]=a1.z;a[7]=a1.w;
            b[0]=b0.x;b[1]=b0.y;b[2]=b0.z;b[3]=b0.w;b[4]=b1.x;b[5]=b1.y;b[6]=b1.z;b[7]=b1.w;
#pragma unroll
            for (int i = 0; i < 8; i++)
#pragma unroll
                for (int j = 0; j < 8; j++) acc[i][j] = fmaf(a[i], b[j], acc[i][j]);
        }
        __syncthreads();
    }

    int nbase = blockIdx.x * 128 + tx * 8;
    float4 bia0 = *(const float4*)(benc + nbase);
    float4 bia1 = *(const float4*)(benc + nbase + 4);
#pragma unroll
    for (int i = 0; i < 8; i++) {
        int m = blockIdx.y * 128 + ty * 8 + i;
        float* o = g_pre + (size_t)m * DICT + nbase;
        float4 r0 = make_float4(acc[i][0] + bia0.x, acc[i][1] + bia0.y,
                                acc[i][2] + bia0.z, acc[i][3] + bia0.w);
        float4 r1 = make_float4(acc[i][4] + bia1.x, acc[i][5] + bia1.y,
                                acc[i][6] + bia1.z, acc[i][7] + bia1.w);
        *(float4*)(o)     = r0;
        *(float4*)(o + 4) = r1;
    }
}

// ---------------- K2: per-row top-64 with exact (fp64) borderline decision ----
__device__ __forceinline__ unsigned sortable_u(float f) {
    unsigned u = __float_as_uint(f);
    return (u & 0x80000000u) ? ~u : (u | 0x80000000u);
}

__global__ __launch_bounds__(256)
void topk_kernel(const float* __restrict__ x,
                 const float* __restrict__ wenc,
                 const float* __restrict__ benc,
                 float* __restrict__ acts_out) {
    extern __shared__ float srow[];                 // DICT floats (dynamic)
    __shared__ unsigned hist[256];
    __shared__ int s_selb, s_ccnt;
    __shared__ int    s_cidx[CAND_CAP];
    __shared__ double s_cval[CAND_CAP];

    const int row  = blockIdx.x;
    const int tid  = threadIdx.x;
    const int wid  = tid >> 5;
    const int lane = tid & 31;
    const float* pre = g_pre + (size_t)row * DICT;
    const float* xr  = x + (size_t)row * D_MODEL;

    for (int i = tid; i < DICT; i += 256) srow[i] = pre[i];
    __syncthreads();

    // ---- radix select: exact 64th-largest key of MY noisy values ----
    unsigned prefix = 0;
    int pbits = 0;
    int need = K_TOP;
#pragma unroll 1
    for (int pass = 0; pass < 4; pass++) {
        hist[tid] = 0;
        __syncthreads();
        int sh = 24 - 8 * pass;
        for (int i = tid; i < DICT; i += 256) {
            unsigned u = sortable_u(srow[i]);
            if (pbits == 0 || (u >> (32 - pbits)) == prefix)
                atomicAdd(&hist[(u >> sh) & 0xFFu], 1u);
        }
        __syncthreads();
        if (tid == 0) {
            int cum = 0, b;
            for (b = 255; b >= 0; --b) {
                int c = (int)hist[b];
                if (cum + c >= need) break;
                cum += c;
            }
            s_selb = b;
            hist[255] = (unsigned)(need - cum);   // reuse as broadcast
        }
        __syncthreads();
        prefix = (prefix << 8) | (unsigned)s_selb;
        need   = (int)hist[255];
        pbits += 8;
        __syncthreads();
    }

    // my 64th-largest value as float
    float v64 = (prefix & 0x80000000u) ? __uint_as_float(prefix & 0x7fffffffu)
                                       : __uint_as_float(~prefix);
    const float candLo = v64 - MARGIN;

    if (tid == 0) s_ccnt = 0;
    __syncthreads();

    // ---- single pass: zero acts, collect candidates (>= candLo) ----
    float* arow = acts_out + (size_t)row * DICT;
    for (int i = tid; i < DICT; i += 256) {
        float f = srow[i];
        arow[i] = 0.f;
        if (f >= candLo) {
            int p = atomicAdd(&s_ccnt, 1);
            if (p < CAND_CAP) s_cidx[p] = i;
        }
    }
    __syncthreads();
    int ccnt = s_ccnt < CAND_CAP ? s_ccnt : CAND_CAP;

    // ---- exact fp64 recompute of candidate pre-activations ----
    for (int c = wid; c < ccnt; c += 8) {
        int fidx = s_cidx[c];
        const float* wr = wenc + (size_t)fidx * D_MODEL;
        double s = 0.0;
#pragma unroll
        for (int t = 0; t < 24; t++) {
            int d = t * 32 + lane;
            s += (double)xr[d] * (double)wr[d];
        }
#pragma unroll
        for (int off = 16; off > 0; off >>= 1)
            s += __shfl_down_sync(0xffffffffu, s, off);
        if (lane == 0) s_cval[c] = s + (double)benc[fidx];
    }
    __syncthreads();

    // ---- exact top-64 among candidates (value desc, index asc) ----
    if (tid == 0) {
        int*   irow = g_idx + (size_t)row * K_TOP;
        float* vrow = g_val + (size_t)row * K_TOP;
        for (int sel = 0; sel < K_TOP; sel++) {
            int best = -1, bidx = 0x7fffffff;
            double bv = -1e300;
            for (int c = 0; c < ccnt; c++) {
                double v = s_cval[c];
                int   ix = s_cidx[c];
                if (v > bv || (v == bv && ix < bidx)) { bv = v; bidx = ix; best = c; }
            }
            if (best < 0) break;
            s_cval[best] = -1e301;               // consume
            float fv = fmaxf(srow[bidx], 0.f);
            irow[sel] = bidx;
            vrow[sel] = fv;
            arow[bidx] = fv;
        }
    }
}

// ---------------- K3: sparse decoder  recon = acts @ W_dec^T ----------------
__global__ void decode_kernel(float* __restrict__ recon) {
    __shared__ int   sidx[K_TOP];
    __shared__ float sval[K_TOP];
    const int row = blockIdx.x;
    const int tid = threadIdx.x;
    if (tid < K_TOP) {
        sidx[tid] = g_idx[(size_t)row * K_TOP + tid];
        sval[tid] = g_val[(size_t)row * K_TOP + tid];
    }
    __syncthreads();

    float a0 = 0.f, a1 = 0.f, a2 = 0.f;
#pragma unroll 8
    for (int j = 0; j < K_TOP; j++) {
        float v = sval[j];
        const float* wr = g_wdt + (size_t)sidx[j] * D_MODEL;
        a0 = fmaf(v, wr[tid],       a0);
        a1 = fmaf(v, wr[tid + 256], a1);
        a2 = fmaf(v, wr[tid + 512], a2);
    }
    float* o = recon + (size_t)row * D_MODEL;
    o[tid]       = a0;
    o[tid + 256] = a1;
    o[tid + 512] = a2;
}

// ---------------- launch ----------------
extern "C" void kernel_launch(void* const* d_in, const int* in_sizes, int n_in,
                              void* d_out, int out_size) {
    const float* x     = (const float*)d_in[0];
    const float* wenc  = (const float*)d_in[1];
    const float* benc  = (const float*)d_in[2];
    const float* wdec  = (const float*)d_in[3];
    (void)in_sizes; (void)n_in; (void)out_size;

    float* out_recon = (float*)d_out;
    float* out_acts  = out_recon + (size_t)B_ROWS * D_MODEL;

    {
        dim3 grid(DICT / 32, D_MODEL / 32);
        dim3 blk(32, 8);
        transpose_wdec_kernel<<<grid, blk>>>(wdec);
    }
    {
        dim3 grid(DICT / 128, B_ROWS / 128);
        sgemm_enc_kernel<<<grid, 256>>>(x, wenc, benc);
    }
    {
        size_t smem = (size_t)DICT * sizeof(float);
        cudaFuncSetAttribute(topk_kernel, cudaFuncAttributeMaxDynamicSharedMemorySize,
                             (int)smem);
        topk_kernel<<<B_ROWS, 256, smem>>>(x, wenc, benc, out_acts);
    }
    decode_kernel<<<B_ROWS, 256>>>(out_recon);
}

// round 4
// speedup vs baseline: 4.3721x; 4.3721x over previous
#include <cuda_runtime.h>
#include <cuda_bf16.h>
#include <stdint.h>

#define B_ROWS   4096
#define D_MODEL  768
#define DICT     24576
#define K_TOP    64
#define CAND_CAP 512
#define MARGIN   0.1f

// ---------------- scratch (device globals) ----------------
__device__ __nv_bfloat16 g_xb[(size_t)B_ROWS * D_MODEL];    // x in bf16
__device__ __nv_bfloat16 g_wb[(size_t)DICT * D_MODEL];      // W_enc in bf16
__device__ __nv_bfloat16 g_preh[(size_t)B_ROWS * DICT];     // screened pre_acts (bf16)
__device__ float g_wdt[(size_t)DICT * D_MODEL];             // W_dec transposed
__device__ int   g_idx[(size_t)B_ROWS * K_TOP];
__device__ float g_val[(size_t)B_ROWS * K_TOP];

__device__ __forceinline__ uint32_t smem_u32(const void* p) {
    uint32_t a;
    asm("{ .reg .u64 t; cvta.to.shared.u64 t, %1; cvt.u32.u64 %0, t; }" : "=r"(a) : "l"(p));
    return a;
}

// ---------------- K0a: fp32 -> bf16 converts ----------------
__global__ void convert_bf16_kernel(const float* __restrict__ src,
                                    __nv_bfloat16* __restrict__ dst, int n4) {
    int i = blockIdx.x * blockDim.x + threadIdx.x;
    if (i < n4) {
        float4 v = ((const float4*)src)[i];
        __nv_bfloat162* o = (__nv_bfloat162*)dst;
        o[2 * i]     = __floats2bfloat162_rn(v.x, v.y);
        o[2 * i + 1] = __floats2bfloat162_rn(v.z, v.w);
    }
}

// ---------------- K0b: transpose W_dec [D][F] -> g_wdt [F][D] ----------------
__global__ void transpose_wdec_kernel(const float* __restrict__ wdec) {
    __shared__ float s[32][33];
    int f0 = blockIdx.x * 32;
    int d0 = blockIdx.y * 32;
    int tx = threadIdx.x, ty = threadIdx.y;
#pragma unroll
    for (int i = 0; i < 4; i++)
        s[ty + i * 8][tx] = wdec[(size_t)(d0 + ty + i * 8) * DICT + f0 + tx];
    __syncthreads();
#pragma unroll
    for (int i = 0; i < 4; i++)
        g_wdt[(size_t)(f0 + ty + i * 8) * D_MODEL + d0 + tx] = s[tx][ty + i * 8];
}

// ---------------- K1: bf16 mma.sync screening GEMM ----------------
// pre[m][n] = sum_k x[m,k] W_enc[n,k] + b[n]; CTA tile 128x128, K-chunk 32.
// smem pitch = 40 bf16 (80B): 80*r mod 128 hits all 8 16B groups -> ldmatrix conflict-free.
#define PITCH 40
#define KCH   32
#define NCHUNKS (D_MODEL / KCH)   // 24

__device__ __forceinline__ void cp16(uint32_t saddr, const void* g) {
    asm volatile("cp.async.ca.shared.global [%0], [%1], 16;" :: "r"(saddr), "l"(g));
}

__global__ __launch_bounds__(256, 1)
void gemm_enc_mma(const float* __restrict__ benc) {
    __shared__ __nv_bfloat16 sA[2][128 * PITCH];
    __shared__ __nv_bfloat16 sB[2][128 * PITCH];
    __shared__ float s_bias[128];

    const int tid  = threadIdx.x;
    const int wid  = tid >> 5;
    const int lane = tid & 31;
    const int wm   = wid & 3;          // 4 warps along M (32 rows each)
    const int wn   = wid >> 2;         // 2 warps along N (64 cols each)
    const int m0 = blockIdx.y * 128;
    const int n0 = blockIdx.x * 128;

    if (tid < 128) s_bias[tid] = benc[n0 + tid];

    const __nv_bfloat16* Ag = g_xb + (size_t)m0 * D_MODEL;
    const __nv_bfloat16* Bg = g_wb + (size_t)n0 * D_MODEL;

    const uint32_t sA0 = smem_u32(&sA[0][0]);
    const uint32_t sB0 = smem_u32(&sB[0][0]);

    // issue stage for chunk ch into buffer buf
    auto issue = [&](int ch, int buf) {
#pragma unroll
        for (int i = 0; i < 2; i++) {
            int seg = tid + (i << 8);          // 0..511
            int r = seg >> 2, c = seg & 3;     // row, 16B chunk
            uint32_t so = (uint32_t)(buf * 128 * PITCH + r * PITCH + c * 8) * 2u;
            cp16(sA0 + so, Ag + (size_t)r * D_MODEL + ch * KCH + c * 8);
            cp16(sB0 + so, Bg + (size_t)r * D_MODEL + ch * KCH + c * 8);
        }
        asm volatile("cp.async.commit_group;" ::: "memory");
    };

    float c[2][8][4];
#pragma unroll
    for (int i = 0; i < 2; i++)
#pragma unroll
        for (int j = 0; j < 8; j++)
#pragma unroll
            for (int q = 0; q < 4; q++) c[i][j][q] = 0.f;

    issue(0, 0);

#pragma unroll 1
    for (int ch = 0; ch < NCHUNKS; ch++) {
        const int buf = ch & 1;
        if (ch + 1 < NCHUNKS) {
            issue(ch + 1, buf ^ 1);
            asm volatile("cp.async.wait_group 1;" ::: "memory");
        } else {
            asm volatile("cp.async.wait_group 0;" ::: "memory");
        }
        __syncthreads();

#pragma unroll
        for (int ks = 0; ks < 2; ks++) {
            uint32_t a[2][4];
#pragma unroll
            for (int ma = 0; ma < 2; ma++) {
                int row = wm * 32 + ma * 16 + (lane & 15);
                int ck  = 2 * ks + (lane >> 4);
                uint32_t ad = sA0 + (uint32_t)(buf * 128 * PITCH + row * PITCH + ck * 8) * 2u;
                asm volatile("ldmatrix.sync.aligned.m8n8.x4.shared.b16 {%0,%1,%2,%3}, [%4];"
                             : "=r"(a[ma][0]), "=r"(a[ma][1]), "=r"(a[ma][2]), "=r"(a[ma][3])
                             : "r"(ad));
            }
            uint32_t b[8][2];
#pragma unroll
            for (int p = 0; p < 4; p++) {
                int row = wn * 64 + p * 16 + (lane & 7) + ((lane >> 4) << 3);
                int ck  = 2 * ks + ((lane >> 3) & 1);
                uint32_t bd = sB0 + (uint32_t)(buf * 128 * PITCH + row * PITCH + ck * 8) * 2u;
                asm volatile("ldmatrix.sync.aligned.m8n8.x4.shared.b16 {%0,%1,%2,%3}, [%4];"
                             : "=r"(b[2 * p][0]), "=r"(b[2 * p][1]),
                               "=r"(b[2 * p + 1][0]), "=r"(b[2 * p + 1][1])
                             : "r"(bd));
            }
#pragma unroll
            for (int ma = 0; ma < 2; ma++)
#pragma unroll
                for (int na = 0; na < 8; na++) {
                    asm volatile(
                        "mma.sync.aligned.m16n8k16.row.col.f32.bf16.bf16.f32 "
                        "{%0,%1,%2,%3}, {%4,%5,%6,%7}, {%8,%9}, {%0,%1,%2,%3};"
                        : "+f"(c[ma][na][0]), "+f"(c[ma][na][1]),
                          "+f"(c[ma][na][2]), "+f"(c[ma][na][3])
                        : "r"(a[ma][0]), "r"(a[ma][1]), "r"(a[ma][2]), "r"(a[ma][3]),
                          "r"(b[na][0]), "r"(b[na][1]));
                }
        }
        __syncthreads();
    }

    // epilogue: bias + bf16 store
#pragma unroll
    for (int ma = 0; ma < 2; ma++) {
#pragma unroll
        for (int na = 0; na < 8; na++) {
            int col = wn * 64 + na * 8 + (lane & 3) * 2;
            float b0 = s_bias[col], b1 = s_bias[col + 1];
            int r0 = m0 + wm * 32 + ma * 16 + (lane >> 2);
            __nv_bfloat162 v0 = __floats2bfloat162_rn(c[ma][na][0] + b0, c[ma][na][1] + b1);
            __nv_bfloat162 v1 = __floats2bfloat162_rn(c[ma][na][2] + b0, c[ma][na][3] + b1);
            *(__nv_bfloat162*)(g_preh + (size_t)r0 * DICT + n0 + col)       = v0;
            *(__nv_bfloat162*)(g_preh + (size_t)(r0 + 8) * DICT + n0 + col) = v1;
        }
    }
}

// ---------------- K2: top-64 screen (bf16 radix) + fp64 exact decision -------
__device__ __forceinline__ unsigned sortable16(unsigned h) {
    return (h & 0x8000u) ? ((~h) & 0xFFFFu) : (h | 0x8000u);
}
__device__ __forceinline__ float key_to_float(unsigned k) {
    unsigned b = (k & 0x8000u) ? (k ^ 0x8000u) : ((~k) & 0xFFFFu);
    return __uint_as_float(b << 16);
}

__global__ __launch_bounds__(256)
void topk_kernel(const float* __restrict__ x,
                 const float* __restrict__ wenc,
                 const float* __restrict__ benc,
                 float* __restrict__ acts_out) {
    extern __shared__ unsigned short skey[];   // DICT u16 keys (48KB)
    __shared__ unsigned hist[256];
    __shared__ int s_b1, s_need, s_ccnt;
    __shared__ int    s_cidx[CAND_CAP];
    __shared__ double s_cval[CAND_CAP];
    __shared__ float  s_x[D_MODEL];

    const int row  = blockIdx.x;
    const int tid  = threadIdx.x;
    const int wid  = tid >> 5;
    const int lane = tid & 31;

    const uint4* pre4 = (const uint4*)(g_preh + (size_t)row * DICT);
    for (int i = tid; i < DICT / 8; i += 256) {
        uint4 v = pre4[i];
        unsigned short* d = skey + i * 8;
        unsigned w;
        w = v.x; d[0] = (unsigned short)sortable16(w & 0xFFFFu); d[1] = (unsigned short)sortable16(w >> 16);
        w = v.y; d[2] = (unsigned short)sortable16(w & 0xFFFFu); d[3] = (unsigned short)sortable16(w >> 16);
        w = v.z; d[4] = (unsigned short)sortable16(w & 0xFFFFu); d[5] = (unsigned short)sortable16(w >> 16);
        w = v.w; d[6] = (unsigned short)sortable16(w & 0xFFFFu); d[7] = (unsigned short)sortable16(w >> 16);
    }
    const float* xr = x + (size_t)row * D_MODEL;
    for (int i = tid; i < D_MODEL; i += 256) s_x[i] = xr[i];
    hist[tid] = 0;
    __syncthreads();

    for (int i = tid; i < DICT; i += 256) atomicAdd(&hist[skey[i] >> 8], 1u);
    __syncthreads();
    if (tid == 0) {
        int cum = 0, b;
        for (b = 255; b >= 0; --b) {
            int cc = (int)hist[b];
            if (cum + cc >= K_TOP) break;
            cum += cc;
        }
        s_b1 = b; s_need = K_TOP - cum;
    }
    __syncthreads();
    const int b1 = s_b1;
    int need = s_need;
    hist[tid] = 0;
    __syncthreads();
    for (int i = tid; i < DICT; i += 256) {
        unsigned k = skey[i];
        if ((int)(k >> 8) == b1) atomicAdd(&hist[k & 0xFFu], 1u);
    }
    __syncthreads();
    if (tid == 0) {
        int cum = 0, b;
        for (b = 255; b >= 0; --b) {
            int cc = (int)hist[b];
            if (cum + cc >= need) break;
            cum += cc;
        }
        s_b1 = ((unsigned)b1 << 8) | (unsigned)b;
        s_ccnt = 0;
    }
    __syncthreads();
    const float candLo = key_to_float((unsigned)s_b1) - MARGIN;

    float* arow = acts_out + (size_t)row * DICT;
    float4 z = make_float4(0.f, 0.f, 0.f, 0.f);
    for (int i = tid; i < DICT / 4; i += 256) ((float4*)arow)[i] = z;
    for (int i = tid; i < DICT; i += 256) {
        float f = key_to_float(skey[i]);
        if (f >= candLo) {
            int p = atomicAdd(&s_ccnt, 1);
            if (p < CAND_CAP) s_cidx[p] = i;
        }
    }
    __syncthreads();
    const int ccnt = s_ccnt < CAND_CAP ? s_ccnt : CAND_CAP;

    for (int cnd = wid; cnd < ccnt; cnd += 8) {
        const int fidx = s_cidx[cnd];
        const float* wr = wenc + (size_t)fidx * D_MODEL;
        double s = 0.0;
#pragma unroll
        for (int t = 0; t < 24; t++) {
            int d = t * 32 + lane;
            s += (double)s_x[d] * (double)wr[d];
        }
#pragma unroll
        for (int off = 16; off > 0; off >>= 1)
            s += __shfl_down_sync(0xffffffffu, s, off);
        if (lane == 0) s_cval[cnd] = s + (double)benc[fidx];
    }
    __syncthreads();

    int* irow   = g_idx + (size_t)row * K_TOP;
    float* vrow = g_val + (size_t)row * K_TOP;
    for (int cnd = tid; cnd < ccnt; cnd += 256) {
        double v = s_cval[cnd];
        int ix = s_cidx[cnd];
        int rank = 0;
        for (int j = 0; j < ccnt; j++) {
            double vj = s_cval[j];
            rank += (vj > v) || (vj == v && s_cidx[j] < ix);
        }
        if (rank < K_TOP) {
            float fv = fmaxf((float)v, 0.f);
            irow[rank] = ix;
            vrow[rank] = fv;
            arow[ix]   = fv;
        }
    }
}

// ---------------- K3: sparse decoder ----------------
__global__ void decode_kernel(float* __restrict__ recon) {
    __shared__ int   sidx[K_TOP];
    __shared__ float sval[K_TOP];
    const int row = blockIdx.x;
    const int tid = threadIdx.x;
    if (tid < K_TOP) {
        sidx[tid] = g_idx[(size_t)row * K_TOP + tid];
        sval[tid] = g_val[(size_t)row * K_TOP + tid];
    }
    __syncthreads();

    float a0 = 0.f, a1 = 0.f, a2 = 0.f;
#pragma unroll 8
    for (int j = 0; j < K_TOP; j++) {
        float v = sval[j];
        const float* wr = g_wdt + (size_t)sidx[j] * D_MODEL;
        a0 = fmaf(v, wr[tid],       a0);
        a1 = fmaf(v, wr[tid + 256], a1);
        a2 = fmaf(v, wr[tid + 512], a2);
    }
    float* o = recon + (size_t)row * D_MODEL;
    o[tid]       = a0;
    o[tid + 256] = a1;
    o[tid + 512] = a2;
}

// ---------------- launch ----------------
extern "C" void kernel_launch(void* const* d_in, const int* in_sizes, int n_in,
                              void* d_out, int out_size) {
    const float* x    = (const float*)d_in[0];
    const float* wenc = (const float*)d_in[1];
    const float* benc = (const float*)d_in[2];
    const float* wdec = (const float*)d_in[3];
    (void)in_sizes; (void)n_in; (void)out_size;

    float* out_recon = (float*)d_out;
    float* out_acts  = out_recon + (size_t)B_ROWS * D_MODEL;

    {
        __nv_bfloat16* xb; cudaGetSymbolAddress((void**)&xb, g_xb);
        __nv_bfloat16* wb; cudaGetSymbolAddress((void**)&wb, g_wb);
        int nx4 = B_ROWS * D_MODEL / 4;
        int nw4 = DICT * D_MODEL / 4;
        convert_bf16_kernel<<<(nx4 + 255) / 256, 256>>>(x, xb, nx4);
        convert_bf16_kernel<<<(nw4 + 255) / 256, 256>>>(wenc, wb, nw4);
    }
    {
        dim3 grid(DICT / 32, D_MODEL / 32);
        dim3 blk(32, 8);
        transpose_wdec_kernel<<<grid, blk>>>(wdec);
    }
    {
        dim3 grid(DICT / 128, B_ROWS / 128);
        gemm_enc_mma<<<grid, 256>>>(benc);
    }
    {
        size_t smem = (size_t)DICT * sizeof(unsigned short);
        cudaFuncSetAttribute(topk_kernel, cudaFuncAttributeMaxDynamicSharedMemorySize,
                             (int)smem);
        topk_kernel<<<B_ROWS, 256, smem>>>(x, wenc, benc, out_acts);
    }
    decode_kernel<<<B_ROWS, 256>>>(out_recon);
}

// round 5
// speedup vs baseline: 4.6634x; 1.0666x over previous
#include <cuda_runtime.h>
#include <cuda_bf16.h>
#include <stdint.h>

#define B_ROWS   4096
#define D_MODEL  768
#define DICT     24576
#define K_TOP    64
#define CAND_CAP 512
#define MARGIN   0.1f

// ---------------- scratch (device globals) ----------------
__device__ __nv_bfloat16 g_xb[(size_t)B_ROWS * D_MODEL];    // x in bf16
__device__ __nv_bfloat16 g_wb[(size_t)DICT * D_MODEL];      // W_enc in bf16
__device__ __nv_bfloat16 g_preh[(size_t)B_ROWS * DICT];     // screened pre_acts (bf16)
__device__ float g_wdt[(size_t)DICT * D_MODEL];             // W_dec transposed
__device__ int   g_idx[(size_t)B_ROWS * K_TOP];
__device__ float g_val[(size_t)B_ROWS * K_TOP];

__device__ __forceinline__ uint32_t smem_u32(const void* p) {
    uint32_t a;
    asm("{ .reg .u64 t; cvta.to.shared.u64 t, %1; cvt.u32.u64 %0, t; }" : "=r"(a) : "l"(p));
    return a;
}

// ---------------- K0a: fp32 -> bf16 converts ----------------
__global__ void convert_bf16_kernel(const float* __restrict__ src,
                                    __nv_bfloat16* __restrict__ dst, int n4) {
    int i = blockIdx.x * blockDim.x + threadIdx.x;
    if (i < n4) {
        float4 v = ((const float4*)src)[i];
        __nv_bfloat162* o = (__nv_bfloat162*)dst;
        o[2 * i]     = __floats2bfloat162_rn(v.x, v.y);
        o[2 * i + 1] = __floats2bfloat162_rn(v.z, v.w);
    }
}

// ---------------- K0b: transpose W_dec [D][F] -> g_wdt [F][D] ----------------
__global__ void transpose_wdec_kernel(const float* __restrict__ wdec) {
    __shared__ float s[32][33];
    int f0 = blockIdx.x * 32;
    int d0 = blockIdx.y * 32;
    int tx = threadIdx.x, ty = threadIdx.y;
#pragma unroll
    for (int i = 0; i < 4; i++)
        s[ty + i * 8][tx] = wdec[(size_t)(d0 + ty + i * 8) * DICT + f0 + tx];
    __syncthreads();
#pragma unroll
    for (int i = 0; i < 4; i++)
        g_wdt[(size_t)(f0 + ty + i * 8) * D_MODEL + d0 + tx] = s[tx][ty + i * 8];
}

// ---------------- K1: bf16 mma.sync screening GEMM ----------------
// CTA tile 128x128, K-chunk 32, 3-stage cp.async pipeline, 2 CTAs/SM.
// smem pitch = 40 bf16 (80B): 80*r mod 128 hits all 8 16B groups -> conflict-free ldmatrix.
#define PITCH 40
#define KCH   32
#define NCHUNKS (D_MODEL / KCH)   // 24
#define STAGE_BYTES (128 * PITCH * 2)          // 10240 per operand per stage
#define GEMM_SMEM   (6 * STAGE_BYTES)          // 3 stages x (A+B) = 61440

__device__ __forceinline__ void cp16(uint32_t saddr, const void* g) {
    asm volatile("cp.async.ca.shared.global [%0], [%1], 16;" :: "r"(saddr), "l"(g));
}

__global__ __launch_bounds__(256, 2)
void gemm_enc_mma(const float* __restrict__ benc) {
    extern __shared__ __align__(128) char dsm[];
    __shared__ float s_bias[128];

    const int tid  = threadIdx.x;
    const int wid  = tid >> 5;
    const int lane = tid & 31;
    const int wm   = wid & 3;          // 4 warps along M (32 rows each)
    const int wn   = wid >> 2;         // 2 warps along N (64 cols each)
    const int m0 = blockIdx.y * 128;
    const int n0 = blockIdx.x * 128;

    if (tid < 128) s_bias[tid] = benc[n0 + tid];

    const __nv_bfloat16* Ag = g_xb + (size_t)m0 * D_MODEL;
    const __nv_bfloat16* Bg = g_wb + (size_t)n0 * D_MODEL;

    const uint32_t sA0 = smem_u32(dsm);                       // 3 A stages
    const uint32_t sB0 = sA0 + 3 * STAGE_BYTES;               // 3 B stages

    auto issue = [&](int ch, int stg) {
#pragma unroll
        for (int i = 0; i < 2; i++) {
            int seg = tid + (i << 8);          // 0..511
            int r = seg >> 2, c = seg & 3;     // row, 16B chunk
            uint32_t so = (uint32_t)stg * STAGE_BYTES + (uint32_t)(r * PITCH + c * 8) * 2u;
            cp16(sA0 + so, Ag + (size_t)r * D_MODEL + ch * KCH + c * 8);
            cp16(sB0 + so, Bg + (size_t)r * D_MODEL + ch * KCH + c * 8);
        }
        asm volatile("cp.async.commit_group;" ::: "memory");
    };

    float c[2][8][4];
#pragma unroll
    for (int i = 0; i < 2; i++)
#pragma unroll
        for (int j = 0; j < 8; j++)
#pragma unroll
            for (int q = 0; q < 4; q++) c[i][j][q] = 0.f;

    issue(0, 0);
    issue(1, 1);

#pragma unroll 1
    for (int ch = 0; ch < NCHUNKS; ch++) {
        const int stg = ch % 3;
        if (ch + 1 < NCHUNKS)
            asm volatile("cp.async.wait_group 1;" ::: "memory");
        else
            asm volatile("cp.async.wait_group 0;" ::: "memory");
        __syncthreads();
        if (ch + 2 < NCHUNKS) issue(ch + 2, (ch + 2) % 3);

        const uint32_t aS = sA0 + (uint32_t)stg * STAGE_BYTES;
        const uint32_t bS = sB0 + (uint32_t)stg * STAGE_BYTES;
#pragma unroll
        for (int ks = 0; ks < 2; ks++) {
            uint32_t a[2][4];
#pragma unroll
            for (int ma = 0; ma < 2; ma++) {
                int row = wm * 32 + ma * 16 + (lane & 15);
                int ck  = 2 * ks + (lane >> 4);
                uint32_t ad = aS + (uint32_t)(row * PITCH + ck * 8) * 2u;
                asm volatile("ldmatrix.sync.aligned.m8n8.x4.shared.b16 {%0,%1,%2,%3}, [%4];"
                             : "=r"(a[ma][0]), "=r"(a[ma][1]), "=r"(a[ma][2]), "=r"(a[ma][3])
                             : "r"(ad));
            }
            uint32_t b[8][2];
#pragma unroll
            for (int p = 0; p < 4; p++) {
                int row = wn * 64 + p * 16 + (lane & 7) + ((lane >> 4) << 3);
                int ck  = 2 * ks + ((lane >> 3) & 1);
                uint32_t bd = bS + (uint32_t)(row * PITCH + ck * 8) * 2u;
                asm volatile("ldmatrix.sync.aligned.m8n8.x4.shared.b16 {%0,%1,%2,%3}, [%4];"
                             : "=r"(b[2 * p][0]), "=r"(b[2 * p][1]),
                               "=r"(b[2 * p + 1][0]), "=r"(b[2 * p + 1][1])
                             : "r"(bd));
            }
#pragma unroll
            for (int ma = 0; ma < 2; ma++)
#pragma unroll
                for (int na = 0; na < 8; na++) {
                    asm volatile(
                        "mma.sync.aligned.m16n8k16.row.col.f32.bf16.bf16.f32 "
                        "{%0,%1,%2,%3}, {%4,%5,%6,%7}, {%8,%9}, {%0,%1,%2,%3};"
                        : "+f"(c[ma][na][0]), "+f"(c[ma][na][1]),
                          "+f"(c[ma][na][2]), "+f"(c[ma][na][3])
                        : "r"(a[ma][0]), "r"(a[ma][1]), "r"(a[ma][2]), "r"(a[ma][3]),
                          "r"(b[na][0]), "r"(b[na][1]));
                }
        }
        __syncthreads();
    }

    // epilogue: bias + bf16 store
#pragma unroll
    for (int ma = 0; ma < 2; ma++) {
#pragma unroll
        for (int na = 0; na < 8; na++) {
            int col = wn * 64 + na * 8 + (lane & 3) * 2;
            float b0 = s_bias[col], b1 = s_bias[col + 1];
            int r0 = m0 + wm * 32 + ma * 16 + (lane >> 2);
            __nv_bfloat162 v0 = __floats2bfloat162_rn(c[ma][na][0] + b0, c[ma][na][1] + b1);
            __nv_bfloat162 v1 = __floats2bfloat162_rn(c[ma][na][2] + b0, c[ma][na][3] + b1);
            *(__nv_bfloat162*)(g_preh + (size_t)r0 * DICT + n0 + col)       = v0;
            *(__nv_bfloat162*)(g_preh + (size_t)(r0 + 8) * DICT + n0 + col) = v1;
        }
    }
}

// ---------------- K2: top-64 screen (bf16 radix) + fp64 exact decision -------
__device__ __forceinline__ unsigned sortable16(unsigned h) {
    return (h & 0x8000u) ? ((~h) & 0xFFFFu) : (h | 0x8000u);
}
__device__ __forceinline__ float key_to_float(unsigned k) {
    unsigned b = (k & 0x8000u) ? (k ^ 0x8000u) : ((~k) & 0xFFFFu);
    return __uint_as_float(b << 16);
}

#define TOPK_T 512

__global__ __launch_bounds__(TOPK_T)
void topk_select(const float* __restrict__ x,
                 const float* __restrict__ wenc,
                 const float* __restrict__ benc) {
    extern __shared__ unsigned short skey[];   // DICT u16 keys (48KB)
    __shared__ unsigned hist[256];
    __shared__ int s_b1, s_need, s_ccnt;
    __shared__ int    s_cidx[CAND_CAP];
    __shared__ double s_cval[CAND_CAP];
    __shared__ float  s_x[D_MODEL];

    const int row  = blockIdx.x;
    const int tid  = threadIdx.x;
    const int wid  = tid >> 5;
    const int lane = tid & 31;

    const uint4* pre4 = (const uint4*)(g_preh + (size_t)row * DICT);
    for (int i = tid; i < DICT / 8; i += TOPK_T) {
        uint4 v = pre4[i];
        unsigned short* d = skey + i * 8;
        unsigned w;
        w = v.x; d[0] = (unsigned short)sortable16(w & 0xFFFFu); d[1] = (unsigned short)sortable16(w >> 16);
        w = v.y; d[2] = (unsigned short)sortable16(w & 0xFFFFu); d[3] = (unsigned short)sortable16(w >> 16);
        w = v.z; d[4] = (unsigned short)sortable16(w & 0xFFFFu); d[5] = (unsigned short)sortable16(w >> 16);
        w = v.w; d[6] = (unsigned short)sortable16(w & 0xFFFFu); d[7] = (unsigned short)sortable16(w >> 16);
    }
    const float* xr = x + (size_t)row * D_MODEL;
    for (int i = tid; i < D_MODEL; i += TOPK_T) s_x[i] = xr[i];
    if (tid < 256) hist[tid] = 0;
    __syncthreads();

    for (int i = tid; i < DICT; i += TOPK_T) atomicAdd(&hist[skey[i] >> 8], 1u);
    __syncthreads();
    if (tid == 0) {
        int cum = 0, b;
        for (b = 255; b >= 0; --b) {
            int cc = (int)hist[b];
            if (cum + cc >= K_TOP) break;
            cum += cc;
        }
        s_b1 = b; s_need = K_TOP - cum;
    }
    __syncthreads();
    const int b1 = s_b1;
    int need = s_need;
    if (tid < 256) hist[tid] = 0;
    __syncthreads();
    for (int i = tid; i < DICT; i += TOPK_T) {
        unsigned k = skey[i];
        if ((int)(k >> 8) == b1) atomicAdd(&hist[k & 0xFFu], 1u);
    }
    __syncthreads();
    if (tid == 0) {
        int cum = 0, b;
        for (b = 255; b >= 0; --b) {
            int cc = (int)hist[b];
            if (cum + cc >= need) break;
            cum += cc;
        }
        s_b1 = ((unsigned)b1 << 8) | (unsigned)b;
        s_ccnt = 0;
    }
    __syncthreads();
    const float candLo = key_to_float((unsigned)s_b1) - MARGIN;

    for (int i = tid; i < DICT; i += TOPK_T) {
        float f = key_to_float(skey[i]);
        if (f >= candLo) {
            int p = atomicAdd(&s_ccnt, 1);
            if (p < CAND_CAP) s_cidx[p] = i;
        }
    }
    __syncthreads();
    const int ccnt = s_ccnt < CAND_CAP ? s_ccnt : CAND_CAP;

    // exact fp64 recompute (16 warps)
    for (int cnd = wid; cnd < ccnt; cnd += TOPK_T / 32) {
        const int fidx = s_cidx[cnd];
        const float* wr = wenc + (size_t)fidx * D_MODEL;
        double s = 0.0;
#pragma unroll
        for (int t = 0; t < 24; t++) {
            int d = t * 32 + lane;
            s += (double)s_x[d] * (double)wr[d];
        }
#pragma unroll
        for (int off = 16; off > 0; off >>= 1)
            s += __shfl_down_sync(0xffffffffu, s, off);
        if (lane == 0) s_cval[cnd] = s + (double)benc[fidx];
    }
    __syncthreads();

    // parallel exact rank (value desc, index asc)
    int* irow   = g_idx + (size_t)row * K_TOP;
    float* vrow = g_val + (size_t)row * K_TOP;
    for (int cnd = tid; cnd < ccnt; cnd += TOPK_T) {
        double v = s_cval[cnd];
        int ix = s_cidx[cnd];
        int rank = 0;
        for (int j = 0; j < ccnt; j++) {
            double vj = s_cval[j];
            rank += (vj > v) || (vj == v && s_cidx[j] < ix);
        }
        if (rank < K_TOP) {
            irow[rank] = ix;
            vrow[rank] = fmaxf((float)v, 0.f);
        }
    }
}

// ---------------- K2b: dense acts = zeros + scatter top-64 ----------------
__global__ __launch_bounds__(256)
void acts_fill(float* __restrict__ acts_out) {
    const int row = blockIdx.x;
    const int tid = threadIdx.x;
    float* arow = acts_out + (size_t)row * DICT;
    float4 z = make_float4(0.f, 0.f, 0.f, 0.f);
#pragma unroll
    for (int i = 0; i < DICT / 4 / 256; i++)
        ((float4*)arow)[tid + i * 256] = z;
    __syncthreads();
    if (tid < K_TOP)
        arow[g_idx[(size_t)row * K_TOP + tid]] = g_val[(size_t)row * K_TOP + tid];
}

// ---------------- K3: sparse decoder ----------------
__global__ void decode_kernel(float* __restrict__ recon) {
    __shared__ int   sidx[K_TOP];
    __shared__ float sval[K_TOP];
    const int row = blockIdx.x;
    const int tid = threadIdx.x;
    if (tid < K_TOP) {
        sidx[tid] = g_idx[(size_t)row * K_TOP + tid];
        sval[tid] = g_val[(size_t)row * K_TOP + tid];
    }
    __syncthreads();

    float a0 = 0.f, a1 = 0.f, a2 = 0.f;
#pragma unroll 8
    for (int j = 0; j < K_TOP; j++) {
        float v = sval[j];
        const float* wr = g_wdt + (size_t)sidx[j] * D_MODEL;
        a0 = fmaf(v, wr[tid],       a0);
        a1 = fmaf(v, wr[tid + 256], a1);
        a2 = fmaf(v, wr[tid + 512], a2);
    }
    float* o = recon + (size_t)row * D_MODEL;
    o[tid]       = a0;
    o[tid + 256] = a1;
    o[tid + 512] = a2;
}

// ---------------- launch ----------------
extern "C" void kernel_launch(void* const* d_in, const int* in_sizes, int n_in,
                              void* d_out, int out_size) {
    const float* x    = (const float*)d_in[0];
    const float* wenc = (const float*)d_in[1];
    const float* benc = (const float*)d_in[2];
    const float* wdec = (const float*)d_in[3];
    (void)in_sizes; (void)n_in; (void)out_size;

    float* out_recon = (float*)d_out;
    float* out_acts  = out_recon + (size_t)B_ROWS * D_MODEL;

    {
        __nv_bfloat16* xb; cudaGetSymbolAddress((void**)&xb, g_xb);
        __nv_bfloat16* wb; cudaGetSymbolAddress((void**)&wb, g_wb);
        int nx4 = B_ROWS * D_MODEL / 4;
        int nw4 = DICT * D_MODEL / 4;
        convert_bf16_kernel<<<(nx4 + 255) / 256, 256>>>(x, xb, nx4);
        convert_bf16_kernel<<<(nw4 + 255) / 256, 256>>>(wenc, wb, nw4);
    }
    {
        dim3 grid(DICT / 32, D_MODEL / 32);
        dim3 blk(32, 8);
        transpose_wdec_kernel<<<grid, blk>>>(wdec);
    }
    {
        cudaFuncSetAttribute(gemm_enc_mma, cudaFuncAttributeMaxDynamicSharedMemorySize,
                             GEMM_SMEM);
        dim3 grid(DICT / 128, B_ROWS / 128);
        gemm_enc_mma<<<grid, 256, GEMM_SMEM>>>(benc);
    }
    {
        size_t smem = (size_t)DICT * sizeof(unsigned short);
        cudaFuncSetAttribute(topk_select, cudaFuncAttributeMaxDynamicSharedMemorySize,
                             (int)smem);
        topk_select<<<B_ROWS, TOPK_T, smem>>>(x, wenc, benc);
    }
    decode_kernel<<<B_ROWS, 256>>>(out_recon);
    acts_fill<<<B_ROWS, 256>>>(out_acts);
}

// round 6
// speedup vs baseline: 8.5587x; 1.8353x over previous
#include <cuda_runtime.h>
#include <cuda_bf16.h>
#include <stdint.h>

#define B_ROWS   4096
#define D_MODEL  768
#define DICT     24576
#define K_TOP    64
#define CAND_CAP 512
#define MARGIN   0.1f

// ---------------- scratch (device globals) ----------------
__device__ __nv_bfloat16 g_xb[(size_t)B_ROWS * D_MODEL];    // x in bf16
__device__ __nv_bfloat16 g_wb[(size_t)DICT * D_MODEL];      // W_enc in bf16
__device__ __nv_bfloat16 g_preh[(size_t)B_ROWS * DICT];     // screened pre_acts (bf16)
__device__ float g_wdt[(size_t)DICT * D_MODEL];             // W_dec transposed
__device__ int   g_idx[(size_t)B_ROWS * K_TOP];
__device__ float g_val[(size_t)B_ROWS * K_TOP];

__device__ __forceinline__ uint32_t smem_u32(const void* p) {
    uint32_t a;
    asm("{ .reg .u64 t; cvta.to.shared.u64 t, %1; cvt.u32.u64 %0, t; }" : "=r"(a) : "l"(p));
    return a;
}

// ---------------- K0a: fp32 -> bf16 converts ----------------
__global__ void convert_bf16_kernel(const float* __restrict__ src,
                                    __nv_bfloat16* __restrict__ dst, int n4) {
    int i = blockIdx.x * blockDim.x + threadIdx.x;
    if (i < n4) {
        float4 v = ((const float4*)src)[i];
        __nv_bfloat162* o = (__nv_bfloat162*)dst;
        o[2 * i]     = __floats2bfloat162_rn(v.x, v.y);
        o[2 * i + 1] = __floats2bfloat162_rn(v.z, v.w);
    }
}

// ---------------- K0b: transpose W_dec [D][F] -> g_wdt [F][D] ----------------
__global__ void transpose_wdec_kernel(const float* __restrict__ wdec) {
    __shared__ float s[32][33];
    int f0 = blockIdx.x * 32;
    int d0 = blockIdx.y * 32;
    int tx = threadIdx.x, ty = threadIdx.y;
#pragma unroll
    for (int i = 0; i < 4; i++)
        s[ty + i * 8][tx] = wdec[(size_t)(d0 + ty + i * 8) * DICT + f0 + tx];
    __syncthreads();
#pragma unroll
    for (int i = 0; i < 4; i++)
        g_wdt[(size_t)(f0 + ty + i * 8) * D_MODEL + d0 + tx] = s[tx][ty + i * 8];
}

// ---------------- K1: bf16 mma.sync screening GEMM (unchanged from R5) -------
#define PITCH 40
#define KCH   32
#define NCHUNKS (D_MODEL / KCH)   // 24
#define STAGE_BYTES (128 * PITCH * 2)
#define GEMM_SMEM   (6 * STAGE_BYTES)

__device__ __forceinline__ void cp16(uint32_t saddr, const void* g) {
    asm volatile("cp.async.ca.shared.global [%0], [%1], 16;" :: "r"(saddr), "l"(g));
}

__global__ __launch_bounds__(256, 2)
void gemm_enc_mma(const float* __restrict__ benc) {
    extern __shared__ __align__(128) char dsm[];
    __shared__ float s_bias[128];

    const int tid  = threadIdx.x;
    const int wid  = tid >> 5;
    const int lane = tid & 31;
    const int wm   = wid & 3;
    const int wn   = wid >> 2;
    const int m0 = blockIdx.y * 128;
    const int n0 = blockIdx.x * 128;

    if (tid < 128) s_bias[tid] = benc[n0 + tid];

    const __nv_bfloat16* Ag = g_xb + (size_t)m0 * D_MODEL;
    const __nv_bfloat16* Bg = g_wb + (size_t)n0 * D_MODEL;

    const uint32_t sA0 = smem_u32(dsm);
    const uint32_t sB0 = sA0 + 3 * STAGE_BYTES;

    auto issue = [&](int ch, int stg) {
#pragma unroll
        for (int i = 0; i < 2; i++) {
            int seg = tid + (i << 8);
            int r = seg >> 2, c = seg & 3;
            uint32_t so = (uint32_t)stg * STAGE_BYTES + (uint32_t)(r * PITCH + c * 8) * 2u;
            cp16(sA0 + so, Ag + (size_t)r * D_MODEL + ch * KCH + c * 8);
            cp16(sB0 + so, Bg + (size_t)r * D_MODEL + ch * KCH + c * 8);
        }
        asm volatile("cp.async.commit_group;" ::: "memory");
    };

    float c[2][8][4];
#pragma unroll
    for (int i = 0; i < 2; i++)
#pragma unroll
        for (int j = 0; j < 8; j++)
#pragma unroll
            for (int q = 0; q < 4; q++) c[i][j][q] = 0.f;

    issue(0, 0);
    issue(1, 1);

#pragma unroll 1
    for (int ch = 0; ch < NCHUNKS; ch++) {
        const int stg = ch % 3;
        if (ch + 1 < NCHUNKS)
            asm volatile("cp.async.wait_group 1;" ::: "memory");
        else
            asm volatile("cp.async.wait_group 0;" ::: "memory");
        __syncthreads();
        if (ch + 2 < NCHUNKS) issue(ch + 2, (ch + 2) % 3);

        const uint32_t aS = sA0 + (uint32_t)stg * STAGE_BYTES;
        const uint32_t bS = sB0 + (uint32_t)stg * STAGE_BYTES;
#pragma unroll
        for (int ks = 0; ks < 2; ks++) {
            uint32_t a[2][4];
#pragma unroll
            for (int ma = 0; ma < 2; ma++) {
                int row = wm * 32 + ma * 16 + (lane & 15);
                int ck  = 2 * ks + (lane >> 4);
                uint32_t ad = aS + (uint32_t)(row * PITCH + ck * 8) * 2u;
                asm volatile("ldmatrix.sync.aligned.m8n8.x4.shared.b16 {%0,%1,%2,%3}, [%4];"
                             : "=r"(a[ma][0]), "=r"(a[ma][1]), "=r"(a[ma][2]), "=r"(a[ma][3])
                             : "r"(ad));
            }
            uint32_t b[8][2];
#pragma unroll
            for (int p = 0; p < 4; p++) {
                int row = wn * 64 + p * 16 + (lane & 7) + ((lane >> 4) << 3);
                int ck  = 2 * ks + ((lane >> 3) & 1);
                uint32_t bd = bS + (uint32_t)(row * PITCH + ck * 8) * 2u;
                asm volatile("ldmatrix.sync.aligned.m8n8.x4.shared.b16 {%0,%1,%2,%3}, [%4];"
                             : "=r"(b[2 * p][0]), "=r"(b[2 * p][1]),
                               "=r"(b[2 * p + 1][0]), "=r"(b[2 * p + 1][1])
                             : "r"(bd));
            }
#pragma unroll
            for (int ma = 0; ma < 2; ma++)
#pragma unroll
                for (int na = 0; na < 8; na++) {
                    asm volatile(
                        "mma.sync.aligned.m16n8k16.row.col.f32.bf16.bf16.f32 "
                        "{%0,%1,%2,%3}, {%4,%5,%6,%7}, {%8,%9}, {%0,%1,%2,%3};"
                        : "+f"(c[ma][na][0]), "+f"(c[ma][na][1]),
                          "+f"(c[ma][na][2]), "+f"(c[ma][na][3])
                        : "r"(a[ma][0]), "r"(a[ma][1]), "r"(a[ma][2]), "r"(a[ma][3]),
                          "r"(b[na][0]), "r"(b[na][1]));
                }
        }
        __syncthreads();
    }

#pragma unroll
    for (int ma = 0; ma < 2; ma++) {
#pragma unroll
        for (int na = 0; na < 8; na++) {
            int col = wn * 64 + na * 8 + (lane & 3) * 2;
            float b0 = s_bias[col], b1 = s_bias[col + 1];
            int r0 = m0 + wm * 32 + ma * 16 + (lane >> 2);
            __nv_bfloat162 v0 = __floats2bfloat162_rn(c[ma][na][0] + b0, c[ma][na][1] + b1);
            __nv_bfloat162 v1 = __floats2bfloat162_rn(c[ma][na][2] + b0, c[ma][na][3] + b1);
            *(__nv_bfloat162*)(g_preh + (size_t)r0 * DICT + n0 + col)       = v0;
            *(__nv_bfloat162*)(g_preh + (size_t)(r0 + 8) * DICT + n0 + col) = v1;
        }
    }
}

// ---------------- K2: top-64 screen + compensated-fp32 exact decision --------
__device__ __forceinline__ unsigned sortable16(unsigned h) {
    return (h & 0x8000u) ? ((~h) & 0xFFFFu) : (h | 0x8000u);
}
__device__ __forceinline__ float key_to_float(unsigned k) {
    unsigned b = (k & 0x8000u) ? (k ^ 0x8000u) : ((~k) & 0xFFFFu);
    return __uint_as_float(b << 16);
}

// TwoSum: s + h = t + e exactly
__device__ __forceinline__ void two_sum(float s, float h, float& t, float& e) {
    t = s + h;
    float z = t - s;
    e = (s - (t - z)) + (h - z);
}

#define TOPK_T 512
#define NHIST  4

__global__ __launch_bounds__(TOPK_T)
void topk_select(const float* __restrict__ x,
                 const float* __restrict__ wenc,
                 const float* __restrict__ benc) {
    extern __shared__ unsigned short skey[];   // DICT u16 keys (48KB)
    __shared__ unsigned hist[NHIST][256];
    __shared__ unsigned hist2[256];
    __shared__ int s_b1, s_need, s_ccnt;
    __shared__ int    s_cidx[CAND_CAP];
    __shared__ double s_cval[CAND_CAP];
    __shared__ float  s_x[D_MODEL];

    const int row  = blockIdx.x;
    const int tid  = threadIdx.x;
    const int wid  = tid >> 5;
    const int lane = tid & 31;

    const uint4* pre4 = (const uint4*)(g_preh + (size_t)row * DICT);
    for (int i = tid; i < DICT / 8; i += TOPK_T) {
        uint4 v = pre4[i];
        unsigned short* d = skey + i * 8;
        unsigned w;
        w = v.x; d[0] = (unsigned short)sortable16(w & 0xFFFFu); d[1] = (unsigned short)sortable16(w >> 16);
        w = v.y; d[2] = (unsigned short)sortable16(w & 0xFFFFu); d[3] = (unsigned short)sortable16(w >> 16);
        w = v.z; d[4] = (unsigned short)sortable16(w & 0xFFFFu); d[5] = (unsigned short)sortable16(w >> 16);
        w = v.w; d[6] = (unsigned short)sortable16(w & 0xFFFFu); d[7] = (unsigned short)sortable16(w >> 16);
    }
    const float* xr = x + (size_t)row * D_MODEL;
    for (int i = tid; i < D_MODEL; i += TOPK_T) s_x[i] = xr[i];
#pragma unroll
    for (int h = 0; h < NHIST; h++)
        if (tid < 256) hist[h][tid] = 0;
    if (tid < 256) hist2[tid] = 0;
    __syncthreads();

    // pass 1: high byte, 4-way replicated histogram to cut mega-bin contention
    const int hsel = wid & (NHIST - 1);
    for (int i = tid; i < DICT; i += TOPK_T) atomicAdd(&hist[hsel][skey[i] >> 8], 1u);
    __syncthreads();
    if (tid < 256) {
        unsigned t = hist[0][tid] + hist[1][tid] + hist[2][tid] + hist[3][tid];
        hist[0][tid] = t;
    }
    __syncthreads();
    if (tid == 0) {
        int cum = 0, b;
        for (b = 255; b >= 0; --b) {
            int cc = (int)hist[0][b];
            if (cum + cc >= K_TOP) break;
            cum += cc;
        }
        s_b1 = b; s_need = K_TOP - cum;
    }
    __syncthreads();
    const int b1 = s_b1;
    int need = s_need;
    for (int i = tid; i < DICT; i += TOPK_T) {
        unsigned k = skey[i];
        if ((int)(k >> 8) == b1) atomicAdd(&hist2[k & 0xFFu], 1u);
    }
    __syncthreads();
    if (tid == 0) {
        int cum = 0, b;
        for (b = 255; b >= 0; --b) {
            int cc = (int)hist2[b];
            if (cum + cc >= need) break;
            cum += cc;
        }
        s_b1 = ((unsigned)b1 << 8) | (unsigned)b;
        s_ccnt = 0;
    }
    __syncthreads();
    const float candLo = key_to_float((unsigned)s_b1) - MARGIN;

    for (int i = tid; i < DICT; i += TOPK_T) {
        float f = key_to_float(skey[i]);
        if (f >= candLo) {
            int p = atomicAdd(&s_ccnt, 1);
            if (p < CAND_CAP) s_cidx[p] = i;
        }
    }
    __syncthreads();
    const int ccnt = s_ccnt < CAND_CAP ? s_ccnt : CAND_CAP;

    // near-exact recompute: compensated fp32 dot (Dot2), fma-pipe only.
    // err ~ (n*u)^2 ~ 2e-9 << decision gaps ~1e-6 -> decisions == fp64 path.
    for (int cnd = wid; cnd < ccnt; cnd += TOPK_T / 32) {
        const int fidx = s_cidx[cnd];
        const float* wr = wenc + (size_t)fidx * D_MODEL;
        float s = 0.f, comp = 0.f;
#pragma unroll
        for (int t = 0; t < 24; t++) {
            int d = t * 32 + lane;
            float a = s_x[d], b = wr[d];
            float h = a * b;
            float r = fmaf(a, b, -h);          // exact product tail
            float tnew, e;
            two_sum(s, h, tnew, e);
            s = tnew;
            comp += e + r;
        }
        // error-tracked cross-lane reduction
#pragma unroll
        for (int off = 16; off > 0; off >>= 1) {
            float s2 = __shfl_down_sync(0xffffffffu, s, off);
            float c2 = __shfl_down_sync(0xffffffffu, comp, off);
            float tnew, e;
            two_sum(s, s2, tnew, e);
            s = tnew;
            comp += c2 + e;
        }
        if (lane == 0)
            s_cval[cnd] = (double)s + (double)comp + (double)benc[fidx];
    }
    __syncthreads();

    // parallel exact rank (value desc, index asc)
    int* irow   = g_idx + (size_t)row * K_TOP;
    float* vrow = g_val + (size_t)row * K_TOP;
    for (int cnd = tid; cnd < ccnt; cnd += TOPK_T) {
        double v = s_cval[cnd];
        int ix = s_cidx[cnd];
        int rank = 0;
        for (int j = 0; j < ccnt; j++) {
            double vj = s_cval[j];
            rank += (vj > v) || (vj == v && s_cidx[j] < ix);
        }
        if (rank < K_TOP) {
            irow[rank] = ix;
            vrow[rank] = fmaxf((float)v, 0.f);
        }
    }
}

// ---------------- K2b: dense acts = zeros + scatter top-64 ----------------
__global__ __launch_bounds__(256)
void acts_fill(float* __restrict__ acts_out) {
    const int row = blockIdx.x;
    const int tid = threadIdx.x;
    float* arow = acts_out + (size_t)row * DICT;
    float4 z = make_float4(0.f, 0.f, 0.f, 0.f);
#pragma unroll
    for (int i = 0; i < DICT / 4 / 256; i++)
        ((float4*)arow)[tid + i * 256] = z;
    __syncthreads();
    if (tid < K_TOP)
        arow[g_idx[(size_t)row * K_TOP + tid]] = g_val[(size_t)row * K_TOP + tid];
}

// ---------------- K3: sparse decoder ----------------
__global__ void decode_kernel(float* __restrict__ recon) {
    __shared__ int   sidx[K_TOP];
    __shared__ float sval[K_TOP];
    const int row = blockIdx.x;
    const int tid = threadIdx.x;
    if (tid < K_TOP) {
        sidx[tid] = g_idx[(size_t)row * K_TOP + tid];
        sval[tid] = g_val[(size_t)row * K_TOP + tid];
    }
    __syncthreads();

    float a0 = 0.f, a1 = 0.f, a2 = 0.f;
#pragma unroll 8
    for (int j = 0; j < K_TOP; j++) {
        float v = sval[j];
        const float* wr = g_wdt + (size_t)sidx[j] * D_MODEL;
        a0 = fmaf(v, wr[tid],       a0);
        a1 = fmaf(v, wr[tid + 256], a1);
        a2 = fmaf(v, wr[tid + 512], a2);
    }
    float* o = recon + (size_t)row * D_MODEL;
    o[tid]       = a0;
    o[tid + 256] = a1;
    o[tid + 512] = a2;
}

// ---------------- launch ----------------
extern "C" void kernel_launch(void* const* d_in, const int* in_sizes, int n_in,
                              void* d_out, int out_size) {
    const float* x    = (const float*)d_in[0];
    const float* wenc = (const float*)d_in[1];
    const float* benc = (const float*)d_in[2];
    const float* wdec = (const float*)d_in[3];
    (void)in_sizes; (void)n_in; (void)out_size;

    float* out_recon = (float*)d_out;
    float* out_acts  = out_recon + (size_t)B_ROWS * D_MODEL;

    {
        __nv_bfloat16* xb; cudaGetSymbolAddress((void**)&xb, g_xb);
        __nv_bfloat16* wb; cudaGetSymbolAddress((void**)&wb, g_wb);
        int nx4 = B_ROWS * D_MODEL / 4;
        int nw4 = DICT * D_MODEL / 4;
        convert_bf16_kernel<<<(nx4 + 255) / 256, 256>>>(x, xb, nx4);
        convert_bf16_kernel<<<(nw4 + 255) / 256, 256>>>(wenc, wb, nw4);
    }
    {
        dim3 grid(DICT / 32, D_MODEL / 32);
        dim3 blk(32, 8);
        transpose_wdec_kernel<<<grid, blk>>>(wdec);
    }
    {
        cudaFuncSetAttribute(gemm_enc_mma, cudaFuncAttributeMaxDynamicSharedMemorySize,
                             GEMM_SMEM);
        dim3 grid(DICT / 128, B_ROWS / 128);
        gemm_enc_mma<<<grid, 256, GEMM_SMEM>>>(benc);
    }
    {
        size_t smem = (size_t)DICT * sizeof(unsigned short);
        cudaFuncSetAttribute(topk_select, cudaFuncAttributeMaxDynamicSharedMemorySize,
                             (int)smem);
        topk_select<<<B_ROWS, TOPK_T, smem>>>(x, wenc, benc);
    }
    decode_kernel<<<B_ROWS, 256>>>(out_recon);
    acts_fill<<<B_ROWS, 256>>>(out_acts);
}